// round 1
// baseline (speedup 1.0000x reference)
#include <cuda_runtime.h>
#include <math.h>

// Problem constants
#define BB    8
#define CC    128
#define HWSZ  262144      // 512*512
#define KK    64
#define BK    512         // B*K
#define NNEG  7
#define PP    4096
#define TAUI  (1.0f/0.07f)

// GEMM tiling
#define QT     32         // queries per block tile
#define PTILE  256        // protos per block
#define PCHUNK 128        // protos staged in smem at once
#define PSTR   132        // padded k-major stride for p tile (16B aligned, conflict-free)
#define NPT    (PP/PTILE) // 16 proto tiles

// Scratch (device globals — no allocation allowed)
__device__ float g_qn[BK*CC];      // normalized query vectors
__device__ float g_rnorm[PP];      // 1/||pool_p||
__device__ float g_pmax[BK*NPT];   // per (query, ptile) max similarity
__device__ float g_loss[BK];       // per-query loss

// ---------------------------------------------------------------------------
// Kernel 1: gather sampled pixels + L2 normalize.  grid=512, block=128
// ---------------------------------------------------------------------------
__global__ void k_gather(const float* __restrict__ qf, const int* __restrict__ qidx) {
    int q = blockIdx.x;
    int c = threadIdx.x;
    int b = q >> 6;
    int idx = qidx[q];
    float v = qf[((size_t)(b * CC + c)) * HWSZ + (size_t)idx];
    float ss = v * v;
    #pragma unroll
    for (int o = 16; o; o >>= 1) ss += __shfl_xor_sync(0xffffffffu, ss, o);
    __shared__ float sred[4];
    if ((c & 31) == 0) sred[c >> 5] = ss;
    __syncthreads();
    float tot = sred[0] + sred[1] + sred[2] + sred[3];
    float inv = 1.0f / fmaxf(sqrtf(tot), 1e-12f);
    g_qn[q * CC + c] = v * inv;
}

// ---------------------------------------------------------------------------
// Kernel 2: pool reciprocal norms.  grid=512, block=256 (warp per proto)
// ---------------------------------------------------------------------------
__global__ void k_poolnorm(const float* __restrict__ pool) {
    int p    = blockIdx.x * 8 + (threadIdx.x >> 5);
    int lane = threadIdx.x & 31;
    float4 v = *(const float4*)(pool + (size_t)p * CC + lane * 4);
    float ss = v.x * v.x + v.y * v.y + v.z * v.z + v.w * v.w;
    #pragma unroll
    for (int o = 16; o; o >>= 1) ss += __shfl_xor_sync(0xffffffffu, ss, o);
    if (lane == 0) g_rnorm[p] = 1.0f / fmaxf(sqrtf(ss), 1e-12f);
}

// ---------------------------------------------------------------------------
// Kernel 3: sim GEMM + running row max.  grid=(16,16), block=256
//   block computes 32 queries x 256 protos; only the max sim per (q, ptile)
//   is kept (the argmax index is not needed: the max sim IS the pos logit).
// ---------------------------------------------------------------------------
__global__ void k_gemm(const float* __restrict__ pool) {
    extern __shared__ float sm[];
    float* q_t = sm;            // [128][QT]   k-major
    float* p_t = sm + CC * QT;  // [128][PSTR] k-major, padded

    int t     = threadIdx.x;
    int qbase = blockIdx.x * QT;
    int pbase = blockIdx.y * PTILE;

    // ---- load q tile transposed: lanes vary q -> conflict-free STS ----
    {
        int q = t & 31, part = t >> 5;          // 8 parts x 16 k each
        const float* src = g_qn + (size_t)(qbase + q) * CC;
        #pragma unroll
        for (int i = 0; i < 4; i++) {
            int k0 = part * 16 + i * 4;
            float4 v = *(const float4*)(src + k0);
            q_t[(k0 + 0) * QT + q] = v.x;
            q_t[(k0 + 1) * QT + q] = v.y;
            q_t[(k0 + 2) * QT + q] = v.z;
            q_t[(k0 + 3) * QT + q] = v.w;
        }
    }

    int qrow = t >> 5;   // 0..7  -> queries 4*qrow..+3
    int pcol = t & 31;   // 0..31 -> protos  4*pcol..+3 (within chunk)

    float bv0 = -3e38f, bv1 = -3e38f, bv2 = -3e38f, bv3 = -3e38f;

    #pragma unroll
    for (int c = 0; c < PTILE / PCHUNK; c++) {
        __syncthreads();
        // ---- stage proto chunk transposed: lanes vary p -> conflict-free ----
        {
            int p = t & 127, half = t >> 7;     // 2 halves x 64 k each
            const float* src = pool + (size_t)(pbase + c * PCHUNK + p) * CC + half * 64;
            #pragma unroll
            for (int i = 0; i < 16; i++) {
                float4 v = *(const float4*)(src + i * 4);
                int k0 = half * 64 + i * 4;
                p_t[(k0 + 0) * PSTR + p] = v.x;
                p_t[(k0 + 1) * PSTR + p] = v.y;
                p_t[(k0 + 2) * PSTR + p] = v.z;
                p_t[(k0 + 3) * PSTR + p] = v.w;
            }
        }
        __syncthreads();

        float acc[4][4];
        #pragma unroll
        for (int i = 0; i < 4; i++)
            #pragma unroll
            for (int j = 0; j < 4; j++) acc[i][j] = 0.0f;

        const float* qp = q_t + 4 * qrow;
        const float* pp = p_t + 4 * pcol;
        #pragma unroll 8
        for (int k = 0; k < CC; k++) {
            float4 qv = *(const float4*)(qp + k * QT);
            float4 pv = *(const float4*)(pp + k * PSTR);
            acc[0][0] += qv.x * pv.x; acc[0][1] += qv.x * pv.y;
            acc[0][2] += qv.x * pv.z; acc[0][3] += qv.x * pv.w;
            acc[1][0] += qv.y * pv.x; acc[1][1] += qv.y * pv.y;
            acc[1][2] += qv.y * pv.z; acc[1][3] += qv.y * pv.w;
            acc[2][0] += qv.z * pv.x; acc[2][1] += qv.z * pv.y;
            acc[2][2] += qv.z * pv.z; acc[2][3] += qv.z * pv.w;
            acc[3][0] += qv.w * pv.x; acc[3][1] += qv.w * pv.y;
            acc[3][2] += qv.w * pv.z; acc[3][3] += qv.w * pv.w;
        }

        float4 rn = *(const float4*)(g_rnorm + pbase + c * PCHUNK + 4 * pcol);
        #pragma unroll
        for (int i = 0; i < 4; i++) {
            float m = fmaxf(fmaxf(acc[i][0] * rn.x, acc[i][1] * rn.y),
                            fmaxf(acc[i][2] * rn.z, acc[i][3] * rn.w));
            if (i == 0) bv0 = fmaxf(bv0, m);
            if (i == 1) bv1 = fmaxf(bv1, m);
            if (i == 2) bv2 = fmaxf(bv2, m);
            if (i == 3) bv3 = fmaxf(bv3, m);
        }
    }

    // max across the 32 pcol lanes (same warp = same qrow)
    #pragma unroll
    for (int o = 16; o; o >>= 1) {
        bv0 = fmaxf(bv0, __shfl_down_sync(0xffffffffu, bv0, o));
        bv1 = fmaxf(bv1, __shfl_down_sync(0xffffffffu, bv1, o));
        bv2 = fmaxf(bv2, __shfl_down_sync(0xffffffffu, bv2, o));
        bv3 = fmaxf(bv3, __shfl_down_sync(0xffffffffu, bv3, o));
    }
    if (pcol == 0) {
        int qg = qbase + 4 * qrow;
        g_pmax[(qg + 0) * NPT + blockIdx.y] = bv0;
        g_pmax[(qg + 1) * NPT + blockIdx.y] = bv1;
        g_pmax[(qg + 2) * NPT + blockIdx.y] = bv2;
        g_pmax[(qg + 3) * NPT + blockIdx.y] = bv3;
    }
}

// ---------------------------------------------------------------------------
// Kernel 4: negatives + softmax CE per query.  grid=512, block=32
// ---------------------------------------------------------------------------
__global__ void k_final(const float* __restrict__ neg) {
    int q    = blockIdx.x;
    int lane = threadIdx.x;

    float v = (lane < NPT) ? g_pmax[q * NPT + lane] : -3e38f;
    #pragma unroll
    for (int o = 16; o; o >>= 1) v = fmaxf(v, __shfl_xor_sync(0xffffffffu, v, o));
    float l0 = v * TAUI;

    float4 qv = *(const float4*)(g_qn + (size_t)q * CC + lane * 4);

    float ln[NNEG];
    #pragma unroll
    for (int n = 0; n < NNEG; n++) {
        float4 nv = *(const float4*)(neg + ((size_t)q * NNEG + n) * CC + lane * 4);
        float dp = qv.x * nv.x + qv.y * nv.y + qv.z * nv.z + qv.w * nv.w;
        float ss = nv.x * nv.x + nv.y * nv.y + nv.z * nv.z + nv.w * nv.w;
        #pragma unroll
        for (int o = 16; o; o >>= 1) {
            dp += __shfl_xor_sync(0xffffffffu, dp, o);
            ss += __shfl_xor_sync(0xffffffffu, ss, o);
        }
        ln[n] = dp / fmaxf(sqrtf(ss), 1e-12f) * TAUI;
    }

    if (lane == 0) {
        float m = l0;
        #pragma unroll
        for (int n = 0; n < NNEG; n++) m = fmaxf(m, ln[n]);
        float se = expf(l0 - m);
        #pragma unroll
        for (int n = 0; n < NNEG; n++) se += expf(ln[n] - m);
        g_loss[q] = logf(se) + m - l0;   // = -(log_softmax[0])
    }
}

// ---------------------------------------------------------------------------
// Kernel 5: mean over 512 losses.  grid=1, block=512
// ---------------------------------------------------------------------------
__global__ void k_reduce(float* __restrict__ out) {
    int t = threadIdx.x;
    float v = g_loss[t];
    #pragma unroll
    for (int o = 16; o; o >>= 1) v += __shfl_xor_sync(0xffffffffu, v, o);
    __shared__ float sred[16];
    if ((t & 31) == 0) sred[t >> 5] = v;
    __syncthreads();
    if (t < 32) {
        float s = (t < 16) ? sred[t] : 0.0f;
        #pragma unroll
        for (int o = 8; o; o >>= 1) s += __shfl_xor_sync(0xffffffffu, s, o);
        if (t == 0) out[0] = s * (1.0f / (float)BK);
    }
}

// ---------------------------------------------------------------------------
extern "C" void kernel_launch(void* const* d_in, const int* in_sizes, int n_in,
                              void* d_out, int out_size) {
    const float* qf   = (const float*)d_in[0];  // [8,128,512,512]
    const float* pool = (const float*)d_in[1];  // [4096,128]
    const float* neg  = (const float*)d_in[2];  // [8,64,7,128]
    const int*   qidx = (const int*)d_in[3];    // [8,64]
    float* out = (float*)d_out;

    const int smem_gemm = (CC * QT + CC * PSTR) * (int)sizeof(float); // 83968 B
    cudaFuncSetAttribute(k_gemm, cudaFuncAttributeMaxDynamicSharedMemorySize, smem_gemm);

    k_gather<<<BK, CC>>>(qf, qidx);
    k_poolnorm<<<PP / 8, 256>>>(pool);
    k_gemm<<<dim3(BK / QT, PP / PTILE), 256, smem_gemm>>>(pool);
    k_final<<<BK, 32>>>(neg);
    k_reduce<<<1, 512>>>(out);
}

// round 2
// speedup vs baseline: 1.0571x; 1.0571x over previous
#include <cuda_runtime.h>
#include <math.h>

// Problem constants
#define BB    8
#define CC    128
#define HWSZ  262144      // 512*512
#define KK    64
#define BK    512         // B*K
#define NNEG  7
#define PP    4096
#define TAUI  (1.0f/0.07f)

// GEMM tiling
#define QT     32         // queries per block tile
#define PTILE  256        // protos per block
#define PCHUNK 128        // protos staged in smem at once
#define PSTR   132        // padded k-major stride for p tile
#define NPT    (PP/PTILE) // 16 proto tiles

// Scratch (device globals — no allocation allowed)
__device__ float g_qn[BK*CC];      // normalized query vectors
__device__ float g_rnorm[PP];      // 1/||pool_p||
__device__ float g_pmax[BK*NPT];   // per (query, ptile) max similarity

// ---- packed fp32x2 helpers (sm_100+) --------------------------------------
__device__ __forceinline__ void ffma2(unsigned long long& acc,
                                      unsigned long long a, unsigned long long b) {
    asm("fma.rn.f32x2 %0, %1, %2, %0;" : "+l"(acc) : "l"(a), "l"(b));
}
__device__ __forceinline__ unsigned long long dup2(float x) {
    unsigned long long r;
    asm("mov.b64 %0, {%1, %1};" : "=l"(r) : "f"(x));
    return r;
}
__device__ __forceinline__ float2 unpack2(unsigned long long v) {
    float2 r;
    asm("mov.b64 {%0, %1}, %2;" : "=f"(r.x), "=f"(r.y) : "l"(v));
    return r;
}

// ---------------------------------------------------------------------------
// Kernel 1: fused prep.  grid=768, block=256
//   blocks [0,512)   : pool reciprocal norms (8 protos each, warp per proto)
//   blocks [512,768) : gather+normalize 2 queries each (128 thr per query)
//   block 512 thread 0 also zeroes the output accumulator.
// ---------------------------------------------------------------------------
__global__ void k_prep(const float* __restrict__ pool,
                       const float* __restrict__ qf,
                       const int* __restrict__ qidx,
                       float* __restrict__ out) {
    int bid = blockIdx.x;
    int t   = threadIdx.x;
    if (bid < 512) {
        int p    = bid * 8 + (t >> 5);
        int lane = t & 31;
        float4 v = *(const float4*)(pool + (size_t)p * CC + lane * 4);
        float ss = v.x * v.x + v.y * v.y + v.z * v.z + v.w * v.w;
        #pragma unroll
        for (int o = 16; o; o >>= 1) ss += __shfl_xor_sync(0xffffffffu, ss, o);
        if (lane == 0) g_rnorm[p] = 1.0f / fmaxf(sqrtf(ss), 1e-12f);
    } else {
        if (bid == 512 && t == 0) out[0] = 0.0f;
        int grp = t >> 7;                       // 0 or 1
        int q   = (bid - 512) * 2 + grp;
        int c   = t & 127;
        int b   = q >> 6;
        int idx = qidx[q];
        float v = qf[((size_t)(b * CC + c)) * HWSZ + (size_t)idx];
        float ss = v * v;
        #pragma unroll
        for (int o = 16; o; o >>= 1) ss += __shfl_xor_sync(0xffffffffu, ss, o);
        __shared__ float sred[8];
        int w = t >> 5;
        if ((t & 31) == 0) sred[w] = ss;
        __syncthreads();
        float tot = sred[grp * 4 + 0] + sred[grp * 4 + 1]
                  + sred[grp * 4 + 2] + sred[grp * 4 + 3];
        float inv = 1.0f / fmaxf(sqrtf(tot), 1e-12f);
        g_qn[q * CC + c] = v * inv;
    }
}

// ---------------------------------------------------------------------------
// Kernel 2: sim GEMM (packed f32x2) + running row max.  grid=(16,16), block=256
//   thread microtile: 8 queries x 2 protos, q-pairs naturally packed in smem.
// ---------------------------------------------------------------------------
__global__ void k_gemm(const float* __restrict__ pool) {
    extern __shared__ float sm[];
    float* q_t = sm;            // [128][QT]   k-major
    float* p_t = sm + CC * QT;  // [128][PSTR] k-major, padded

    int t     = threadIdx.x;
    int qbase = blockIdx.x * QT;
    int pbase = blockIdx.y * PTILE;

    // ---- load q tile transposed (lanes vary q -> conflict-free STS) ----
    {
        int q = t & 31, part = t >> 5;          // 8 parts x 16 k each
        const float* src = g_qn + (size_t)(qbase + q) * CC;
        #pragma unroll
        for (int i = 0; i < 4; i++) {
            int k0 = part * 16 + i * 4;
            float4 v = *(const float4*)(src + k0);
            q_t[(k0 + 0) * QT + q] = v.x;
            q_t[(k0 + 1) * QT + q] = v.y;
            q_t[(k0 + 2) * QT + q] = v.z;
            q_t[(k0 + 3) * QT + q] = v.w;
        }
    }

    int qrow = t >> 6;   // 0..3  -> queries 8*qrow .. +7
    int pcol = t & 63;   // 0..63 -> protos  2*pcol, 2*pcol+1 (within chunk)

    float bv[8];
    #pragma unroll
    for (int i = 0; i < 8; i++) bv[i] = -3e38f;

    #pragma unroll
    for (int c = 0; c < PTILE / PCHUNK; c++) {
        __syncthreads();
        // ---- stage proto chunk transposed (lanes vary p -> conflict-free) ----
        {
            int p = t & 127, half = t >> 7;     // 2 halves x 64 k each
            const float* src = pool + (size_t)(pbase + c * PCHUNK + p) * CC + half * 64;
            #pragma unroll
            for (int i = 0; i < 16; i++) {
                float4 v = *(const float4*)(src + i * 4);
                int k0 = half * 64 + i * 4;
                p_t[(k0 + 0) * PSTR + p] = v.x;
                p_t[(k0 + 1) * PSTR + p] = v.y;
                p_t[(k0 + 2) * PSTR + p] = v.z;
                p_t[(k0 + 3) * PSTR + p] = v.w;
            }
        }
        __syncthreads();

        unsigned long long acc[4][2];
        #pragma unroll
        for (int i = 0; i < 4; i++) { acc[i][0] = 0ull; acc[i][1] = 0ull; }

        const float* qp = q_t + 8 * qrow;
        const float* pp = p_t + 2 * pcol;
        #pragma unroll 8
        for (int k = 0; k < CC; k++) {
            ulonglong2 qa = *(const ulonglong2*)(qp + k * QT);      // (q0,q1),(q2,q3)
            ulonglong2 qb = *(const ulonglong2*)(qp + k * QT + 4);  // (q4,q5),(q6,q7)
            float2 pv = *(const float2*)(pp + k * PSTR);
            unsigned long long d0 = dup2(pv.x);
            unsigned long long d1 = dup2(pv.y);
            ffma2(acc[0][0], qa.x, d0); ffma2(acc[0][1], qa.x, d1);
            ffma2(acc[1][0], qa.y, d0); ffma2(acc[1][1], qa.y, d1);
            ffma2(acc[2][0], qb.x, d0); ffma2(acc[2][1], qb.x, d1);
            ffma2(acc[3][0], qb.y, d0); ffma2(acc[3][1], qb.y, d1);
        }

        float r0 = g_rnorm[pbase + c * PCHUNK + 2 * pcol];
        float r1 = g_rnorm[pbase + c * PCHUNK + 2 * pcol + 1];
        #pragma unroll
        for (int i = 0; i < 4; i++) {
            float2 a0 = unpack2(acc[i][0]);   // (q=8qrow+2i, p0), (q+1, p0)
            float2 a1 = unpack2(acc[i][1]);
            bv[2*i]   = fmaxf(bv[2*i],   fmaxf(a0.x * r0, a1.x * r1));
            bv[2*i+1] = fmaxf(bv[2*i+1], fmaxf(a0.y * r0, a1.y * r1));
        }
    }

    // max across the 32 lanes of each warp (warp shares qrow)
    #pragma unroll
    for (int o = 16; o; o >>= 1)
        #pragma unroll
        for (int i = 0; i < 8; i++)
            bv[i] = fmaxf(bv[i], __shfl_down_sync(0xffffffffu, bv[i], o));

    // combine the two warps that share each qrow via smem, write g_pmax
    __syncthreads();
    int w = t >> 5;
    if ((t & 31) == 0) {
        #pragma unroll
        for (int i = 0; i < 8; i++) q_t[w * 8 + i] = bv[i];
    }
    __syncthreads();
    if (t < 32) {
        int r = t >> 3, qi = t & 7;
        float m = fmaxf(q_t[(2*r) * 8 + qi], q_t[(2*r+1) * 8 + qi]);
        g_pmax[(qbase + 8*r + qi) * NPT + blockIdx.y] = m;
    }
}

// ---------------------------------------------------------------------------
// Kernel 3: negatives + softmax CE + mean.  grid=64, block=256 (warp=query)
// ---------------------------------------------------------------------------
__global__ void k_final(const float* __restrict__ neg, float* __restrict__ out) {
    int q    = blockIdx.x * 8 + (threadIdx.x >> 5);
    int lane = threadIdx.x & 31;

    float v = (lane < NPT) ? g_pmax[q * NPT + lane] : -3e38f;
    #pragma unroll
    for (int o = 16; o; o >>= 1) v = fmaxf(v, __shfl_xor_sync(0xffffffffu, v, o));
    float l0 = v * TAUI;

    float4 qv = *(const float4*)(g_qn + (size_t)q * CC + lane * 4);

    float ln[NNEG];
    #pragma unroll
    for (int n = 0; n < NNEG; n++) {
        float4 nv = *(const float4*)(neg + ((size_t)q * NNEG + n) * CC + lane * 4);
        float dp = qv.x * nv.x + qv.y * nv.y + qv.z * nv.z + qv.w * nv.w;
        float ss = nv.x * nv.x + nv.y * nv.y + nv.z * nv.z + nv.w * nv.w;
        #pragma unroll
        for (int o = 16; o; o >>= 1) {
            dp += __shfl_xor_sync(0xffffffffu, dp, o);
            ss += __shfl_xor_sync(0xffffffffu, ss, o);
        }
        ln[n] = dp / fmaxf(sqrtf(ss), 1e-12f) * TAUI;
    }

    if (lane == 0) {
        float m = l0;
        #pragma unroll
        for (int n = 0; n < NNEG; n++) m = fmaxf(m, ln[n]);
        float se = expf(l0 - m);
        #pragma unroll
        for (int n = 0; n < NNEG; n++) se += expf(ln[n] - m);
        float loss = logf(se) + m - l0;          // = -(log_softmax[0])
        atomicAdd(out, loss * (1.0f / (float)BK));
    }
}

// ---------------------------------------------------------------------------
extern "C" void kernel_launch(void* const* d_in, const int* in_sizes, int n_in,
                              void* d_out, int out_size) {
    const float* qf   = (const float*)d_in[0];  // [8,128,512,512]
    const float* pool = (const float*)d_in[1];  // [4096,128]
    const float* neg  = (const float*)d_in[2];  // [8,64,7,128]
    const int*   qidx = (const int*)d_in[3];    // [8,64]
    float* out = (float*)d_out;

    const int smem_gemm = (CC * QT + CC * PSTR) * (int)sizeof(float); // 83968 B
    cudaFuncSetAttribute(k_gemm, cudaFuncAttributeMaxDynamicSharedMemorySize, smem_gemm);

    k_prep<<<768, 256>>>(pool, qf, qidx, out);
    k_gemm<<<dim3(BK / QT, PP / PTILE), 256, smem_gemm>>>(pool);
    k_final<<<BK / 8, 256>>>(neg, out);
}